// round 5
// baseline (speedup 1.0000x reference)
#include <cuda_runtime.h>
#include <math.h>

#define BATCH   256
#define NCOLS   20000
#define DLAT    400
#define SEGS    4
#define SEG_ELEMS (NCOLS / SEGS)          // 5000
#define BIG_BLOCKS (BATCH * SEGS)         // 1024
#define THREADS 256

// Per-segment partials: [BIG_BLOCKS][8]:
//   0: sum exp(recon)  1: sum exp(text)  2: sum exp(rec)
//   3: dot(recon,x)    4: dot(text,x)    5: dot(rec,x)
//   6: sum x           7: pad
__device__ float g_seg[BIG_BLOCKS * 8];
// Per-row small partials: [BATCH][4]: ws_row, kld1_row, kld2_row, pad
__device__ float g_small[BATCH * 4];

__device__ __forceinline__ float warp_sum(float v) {
    #pragma unroll
    for (int o = 16; o > 0; o >>= 1) v += __shfl_down_sync(0xFFFFFFFFu, v, o);
    return v;
}

// Reduce `val` over the whole 256-thread block; result valid on tid==0.
// `slot` selects a distinct shared buffer (call sites must all execute uniformly).
__device__ __forceinline__ float block_sum(float v, float* sbuf) {
    int lane = threadIdx.x & 31;
    int warp = threadIdx.x >> 5;
    v = warp_sum(v);
    if (lane == 0) sbuf[warp] = v;
    __syncthreads();
    float r = 0.0f;
    if (warp == 0) {
        r = (lane < (THREADS / 32)) ? sbuf[lane] : 0.0f;
        r = warp_sum(r);
    }
    __syncthreads();
    return r;
}

__global__ __launch_bounds__(THREADS) void partial_kernel(
    const float* __restrict__ recon,
    const float* __restrict__ x,
    const float* __restrict__ mu,
    const float* __restrict__ logvar,
    const float* __restrict__ ltext,
    const float* __restrict__ lrec,
    const float* __restrict__ pmu,
    const float* __restrict__ plogvar)
{
    __shared__ float sbuf[THREADS / 32];
    const int bid = blockIdx.x;
    const int tid = threadIdx.x;

    if (bid < BIG_BLOCKS) {
        const int row = bid >> 2;
        const int seg = bid & 3;
        const size_t base = (size_t)row * NCOLS + (size_t)seg * SEG_ELEMS;
        // base*4 bytes: row stride 80000 B and seg stride 20000 B are both
        // 16-byte multiples -> aligned float4.
        const float4* __restrict__ x4 = (const float4*)(x + base);
        const float4* __restrict__ m4 = (const float4*)(recon + base);
        const float4* __restrict__ t4 = (const float4*)(ltext + base);
        const float4* __restrict__ r4 = (const float4*)(lrec + base);
        const int n4 = SEG_ELEMS / 4;   // 1250

        float se_m = 0.f, se_t = 0.f, se_r = 0.f;
        float dm = 0.f, dt = 0.f, dr = 0.f, sx = 0.f;
        for (int i = tid; i < n4; i += THREADS) {
            float4 xv = x4[i];
            float4 mv = m4[i];
            float4 tv = t4[i];
            float4 rv = r4[i];
            se_m += __expf(mv.x) + __expf(mv.y) + __expf(mv.z) + __expf(mv.w);
            se_t += __expf(tv.x) + __expf(tv.y) + __expf(tv.z) + __expf(tv.w);
            se_r += __expf(rv.x) + __expf(rv.y) + __expf(rv.z) + __expf(rv.w);
            dm += mv.x * xv.x + mv.y * xv.y + mv.z * xv.z + mv.w * xv.w;
            dt += tv.x * xv.x + tv.y * xv.y + tv.z * xv.z + tv.w * xv.w;
            dr += rv.x * xv.x + rv.y * xv.y + rv.z * xv.z + rv.w * xv.w;
            sx += xv.x + xv.y + xv.z + xv.w;
        }
        float vals[7] = {se_m, se_t, se_r, dm, dt, dr, sx};
        #pragma unroll
        for (int k = 0; k < 7; k++) {
            float r = block_sum(vals[k], sbuf);
            if (tid == 0) g_seg[bid * 8 + k] = r;
        }
    } else {
        const int row = bid - BIG_BLOCKS;
        const float* __restrict__ lv  = logvar  + (size_t)row * DLAT;
        const float* __restrict__ plv = plogvar + (size_t)row * DLAT;
        const float* __restrict__ m   = mu      + (size_t)row * DLAT;
        const float* __restrict__ pm  = pmu     + (size_t)row * DLAT;

        float ws = 0.f, k1 = 0.f, k2 = 0.f;
        for (int i = tid; i < DLAT; i += THREADS) {
            float l  = lv[i];
            float pl = plv[i];
            float el  = __expf(l);
            float epl = __expf(pl);
            float d = m[i] - pm[i];
            // tr1 + tr2 - 2*tr(sqrt(S1*S2)) + ||mu-pmu||^2, diagonal covs
            ws += d * d + el + epl - 2.0f * __expf(0.5f * (l + pl));
            k1 += 1.0f + l  - el;
            k2 += 1.0f + pl - epl;
        }
        float vals[3] = {ws, k1, k2};
        #pragma unroll
        for (int k = 0; k < 3; k++) {
            float r = block_sum(vals[k], sbuf);
            if (tid == 0) g_small[row * 4 + k] = r;
        }
    }
}

__global__ __launch_bounds__(THREADS) void finalize_kernel(float* __restrict__ out) {
    __shared__ float sbuf[THREADS / 32];
    const int b = threadIdx.x;   // one thread per batch row (THREADS == BATCH)

    float se_m = 0.f, se_t = 0.f, se_r = 0.f;
    float dm = 0.f, dt = 0.f, dr = 0.f, sx = 0.f;
    #pragma unroll
    for (int s = 0; s < SEGS; s++) {
        const float* p = &g_seg[(b * SEGS + s) * 8];
        se_m += p[0]; se_t += p[1]; se_r += p[2];
        dm   += p[3]; dt   += p[4]; dr   += p[5];
        sx   += p[6];
    }
    // row contribution of sum_n log_softmax(v)*x = dot - lse*sum(x)
    float bm = dm - logf(se_m) * sx;
    float bt = dt - logf(se_t) * sx;
    float br = dr - logf(se_r) * sx;
    float ws = g_small[b * 4 + 0];
    float k1 = g_small[b * 4 + 1];
    float k2 = g_small[b * 4 + 2];

    float S_bm = block_sum(bm, sbuf);
    float S_bt = block_sum(bt, sbuf);
    float S_br = block_sum(br, sbuf);
    float S_ws = block_sum(ws, sbuf);
    float S_k1 = block_sum(k1, sbuf);
    float S_k2 = block_sum(k2, sbuf);

    if (b == 0) {
        const float invBN = 1.0f / ((float)BATCH * (float)NCOLS);
        const float invBD = 1.0f / ((float)BATCH * (float)DLAT);
        float BCE_merged = -S_bm * invBN;
        float BCE_text   = -S_bt * invBN;
        float BCE_rec    = -S_br * invBN;
        float BCE  = (BCE_merged + BCE_text + BCE_rec) * (1.0f / 3.0f);
        float KLD1 = -0.5f * S_k1 * invBD;
        float KLD2 = -0.5f * S_k2 * invBD;
        float wloss = S_ws / (float)BATCH;
        float l = BCE + 0.5f * (KLD1 + KLD2) + wloss;
        out[0] = l;
        out[1] = BCE;
        out[2] = wloss;
        out[3] = BCE_rec;
        out[4] = BCE_text;
        out[5] = BCE_merged;
    }
}

extern "C" void kernel_launch(void* const* d_in, const int* in_sizes, int n_in,
                              void* d_out, int out_size) {
    const float* recon   = (const float*)d_in[0];
    const float* x       = (const float*)d_in[1];
    const float* mu      = (const float*)d_in[2];
    const float* logvar  = (const float*)d_in[3];
    const float* ltext   = (const float*)d_in[4];
    const float* lrec    = (const float*)d_in[5];
    const float* pmu     = (const float*)d_in[6];
    const float* plogvar = (const float*)d_in[7];
    float* out = (float*)d_out;

    partial_kernel<<<BIG_BLOCKS + BATCH, THREADS>>>(
        recon, x, mu, logvar, ltext, lrec, pmu, plogvar);
    finalize_kernel<<<1, THREADS>>>(out);
}

// round 8
// speedup vs baseline: 1.1180x; 1.1180x over previous
#include <cuda_runtime.h>
#include <math.h>

#define BATCH   256
#define NCOLS   20000
#define DLAT    400
#define SEGS    4
#define SEG_ELEMS (NCOLS / SEGS)          // 5000
#define BIG_BLOCKS (BATCH * SEGS)         // 1024
#define TOTAL_BLOCKS (BIG_BLOCKS + BATCH) // 1280
#define THREADS 256

// Per-segment partials: [BIG_BLOCKS][8]:
//   0: sum exp(recon)  1: sum exp(text)  2: sum exp(rec)
//   3: dot(recon,x)    4: dot(text,x)    5: dot(rec,x)
//   6: sum x           7: pad
__device__ float g_seg[BIG_BLOCKS * 8];
// Per-row small partials: [BATCH][4]: ws_row, kld1_row, kld2_row, pad
__device__ float g_small[BATCH * 4];
// Block-completion counter (reset to 0 by the last block each call ->
// deterministic across graph replays).
__device__ int g_count = 0;

__device__ __forceinline__ float warp_sum(float v) {
    #pragma unroll
    for (int o = 16; o > 0; o >>= 1) v += __shfl_down_sync(0xFFFFFFFFu, v, o);
    return v;
}

// Reduce over the whole 256-thread block; result valid on tid==0.
__device__ __forceinline__ float block_sum(float v, float* sbuf) {
    int lane = threadIdx.x & 31;
    int warp = threadIdx.x >> 5;
    v = warp_sum(v);
    if (lane == 0) sbuf[warp] = v;
    __syncthreads();
    float r = 0.0f;
    if (warp == 0) {
        r = (lane < (THREADS / 32)) ? sbuf[lane] : 0.0f;
        r = warp_sum(r);
    }
    __syncthreads();
    return r;
}

__global__ __launch_bounds__(THREADS) void fused_kernel(
    const float* __restrict__ recon,
    const float* __restrict__ x,
    const float* __restrict__ mu,
    const float* __restrict__ logvar,
    const float* __restrict__ ltext,
    const float* __restrict__ lrec,
    const float* __restrict__ pmu,
    const float* __restrict__ plogvar,
    float* __restrict__ out)
{
    __shared__ float sbuf[THREADS / 32];
    __shared__ bool s_is_last;
    const int bid = blockIdx.x;
    const int tid = threadIdx.x;

    // ─────────── Phase 1: per-block partial sums ───────────
    if (bid < BIG_BLOCKS) {
        const int row = bid >> 2;
        const int seg = bid & 3;
        const size_t base = (size_t)row * NCOLS + (size_t)seg * SEG_ELEMS;
        // Row stride 80000 B and seg stride 20000 B are 16B multiples -> aligned float4.
        const float4* __restrict__ x4 = (const float4*)(x + base);
        const float4* __restrict__ m4 = (const float4*)(recon + base);
        const float4* __restrict__ t4 = (const float4*)(ltext + base);
        const float4* __restrict__ r4 = (const float4*)(lrec + base);
        const int n4 = SEG_ELEMS / 4;   // 1250

        float se_m = 0.f, se_t = 0.f, se_r = 0.f;
        float dm = 0.f, dt = 0.f, dr = 0.f, sx = 0.f;
        for (int i = tid; i < n4; i += THREADS) {
            float4 xv = x4[i];
            float4 mv = m4[i];
            float4 tv = t4[i];
            float4 rv = r4[i];
            se_m += __expf(mv.x) + __expf(mv.y) + __expf(mv.z) + __expf(mv.w);
            se_t += __expf(tv.x) + __expf(tv.y) + __expf(tv.z) + __expf(tv.w);
            se_r += __expf(rv.x) + __expf(rv.y) + __expf(rv.z) + __expf(rv.w);
            dm += mv.x * xv.x + mv.y * xv.y + mv.z * xv.z + mv.w * xv.w;
            dt += tv.x * xv.x + tv.y * xv.y + tv.z * xv.z + tv.w * xv.w;
            dr += rv.x * xv.x + rv.y * xv.y + rv.z * xv.z + rv.w * xv.w;
            sx += xv.x + xv.y + xv.z + xv.w;
        }
        float vals[7] = {se_m, se_t, se_r, dm, dt, dr, sx};
        #pragma unroll
        for (int k = 0; k < 7; k++) {
            float r = block_sum(vals[k], sbuf);
            if (tid == 0) g_seg[bid * 8 + k] = r;
        }
    } else {
        const int row = bid - BIG_BLOCKS;
        const float* __restrict__ lv  = logvar  + (size_t)row * DLAT;
        const float* __restrict__ plv = plogvar + (size_t)row * DLAT;
        const float* __restrict__ m   = mu      + (size_t)row * DLAT;
        const float* __restrict__ pm  = pmu     + (size_t)row * DLAT;

        float ws = 0.f, k1 = 0.f, k2 = 0.f;
        for (int i = tid; i < DLAT; i += THREADS) {
            float l  = lv[i];
            float pl = plv[i];
            float el  = __expf(l);
            float epl = __expf(pl);
            float d = m[i] - pm[i];
            // diag covs: tr1 + tr2 - 2*tr(sqrt(S1*S2)) + ||mu-pmu||^2
            ws += d * d + el + epl - 2.0f * __expf(0.5f * (l + pl));
            k1 += 1.0f + l  - el;
            k2 += 1.0f + pl - epl;
        }
        float vals[3] = {ws, k1, k2};
        #pragma unroll
        for (int k = 0; k < 3; k++) {
            float r = block_sum(vals[k], sbuf);
            if (tid == 0) g_small[row * 4 + k] = r;
        }
    }

    // ─────────── Phase 2: last block finalizes ───────────
    __threadfence();            // make this block's g_seg/g_small writes visible
    __syncthreads();            // all stores issued before the arrive
    if (tid == 0) {
        int prev = atomicAdd(&g_count, 1);
        s_is_last = (prev == TOTAL_BLOCKS - 1);
    }
    __syncthreads();
    if (!s_is_last) return;

    // This block observed all other blocks' arrivals (each preceded by its own
    // __threadfence), so all partials are visible. One thread per batch row.
    const int b = tid;          // THREADS == BATCH
    float se_m = 0.f, se_t = 0.f, se_r = 0.f;
    float dm = 0.f, dt = 0.f, dr = 0.f, sx = 0.f;
    #pragma unroll
    for (int s = 0; s < SEGS; s++) {
        const float* p = &g_seg[(b * SEGS + s) * 8];
        se_m += p[0]; se_t += p[1]; se_r += p[2];
        dm   += p[3]; dt   += p[4]; dr   += p[5];
        sx   += p[6];
    }
    // row contribution of sum_n log_softmax(v)*x = dot - lse*sum(x)
    float bm = dm - logf(se_m) * sx;
    float bt = dt - logf(se_t) * sx;
    float br = dr - logf(se_r) * sx;
    float ws = g_small[b * 4 + 0];
    float k1 = g_small[b * 4 + 1];
    float k2 = g_small[b * 4 + 2];

    float S_bm = block_sum(bm, sbuf);
    float S_bt = block_sum(bt, sbuf);
    float S_br = block_sum(br, sbuf);
    float S_ws = block_sum(ws, sbuf);
    float S_k1 = block_sum(k1, sbuf);
    float S_k2 = block_sum(k2, sbuf);

    if (b == 0) {
        const float invBN = 1.0f / ((float)BATCH * (float)NCOLS);
        const float invBD = 1.0f / ((float)BATCH * (float)DLAT);
        float BCE_merged = -S_bm * invBN;
        float BCE_text   = -S_bt * invBN;
        float BCE_rec    = -S_br * invBN;
        float BCE  = (BCE_merged + BCE_text + BCE_rec) * (1.0f / 3.0f);
        float KLD1 = -0.5f * S_k1 * invBD;
        float KLD2 = -0.5f * S_k2 * invBD;
        float wloss = S_ws / (float)BATCH;
        float l = BCE + 0.5f * (KLD1 + KLD2) + wloss;
        out[0] = l;
        out[1] = BCE;
        out[2] = wloss;
        out[3] = BCE_rec;
        out[4] = BCE_text;
        out[5] = BCE_merged;
        g_count = 0;            // reset for next call / graph replay
    }
}

extern "C" void kernel_launch(void* const* d_in, const int* in_sizes, int n_in,
                              void* d_out, int out_size) {
    const float* recon   = (const float*)d_in[0];
    const float* x       = (const float*)d_in[1];
    const float* mu      = (const float*)d_in[2];
    const float* logvar  = (const float*)d_in[3];
    const float* ltext   = (const float*)d_in[4];
    const float* lrec    = (const float*)d_in[5];
    const float* pmu     = (const float*)d_in[6];
    const float* plogvar = (const float*)d_in[7];
    float* out = (float*)d_out;

    fused_kernel<<<TOTAL_BLOCKS, THREADS>>>(
        recon, x, mu, logvar, ltext, lrec, pmu, plogvar, out);
}